// round 13
// baseline (speedup 1.0000x reference)
#include <cuda_runtime.h>
#include <cuda_bf16.h>
#include <mma.h>
#include <math.h>

using namespace nvcuda;
typedef __nv_bfloat16 bf16;

// ---------------- problem constants ----------------
#define NNODES 50000
#define NEDGES 800000
#define NBLK   ((NNODES + 255) / 256)   // 196

// ---------------- device scratch ----------------
__device__ unsigned g_any;
__device__ int   g_cnt[NNODES];
__device__ int   g_rowptr[NNODES + 1];
__device__ int   g_ctr[NNODES];
__device__ int   g_csr[NEDGES];
__device__ float g_dinv[NNODES];
__device__ int   g_bsum[NBLK];

__device__ bf16  g_h32b [NNODES * 32];
__device__ bf16  g_h64b [NNODES * 64];
__device__ bf16  g_h128b[NNODES * 128];   // relu(mlp3)  (NO dinv — applied in agg)
__device__ bf16  g_u128 [NNODES * 128];   // aggregated
__device__ bf16  g_a256 [NNODES * 256];   // relu(gcn1) * dinv
__device__ bf16  g_u256 [NNODES * 256];
__device__ bf16  g_a512 [NNODES * 512];   // relu(gcn2) * dinv
__device__ float g_t50  [NNODES * 64];    // padded, pre-agg logits

__device__ bf16  g_wb2[32 * 64];
__device__ bf16  g_wb3[64 * 128];
__device__ bf16  g_wg1[128 * 256];
__device__ bf16  g_wg2[256 * 512];
__device__ bf16  g_wg3[512 * 64];         // zero-padded 50 -> 64

// ---------------- edge-index dtype handling ----------------
__device__ __forceinline__ int load_idx(const void* p, long long e) {
    if (g_any == 0u) return (int)((const long long*)p)[e];   // int64 data
    return ((const int*)p)[e];
}

#define FTHREADS (NBLK * 256)   // 50176

// ---------------- detect + zero counters (must precede k_front's atomics) ----------------
__global__ void k_detect(const unsigned* __restrict__ e32) {
    int gid = blockIdx.x * 256 + threadIdx.x;
    if (gid < NNODES) g_cnt[gid] = 0;
    unsigned local = (gid < 16384) ? e32[2 * gid + 1] : 0u;
    #pragma unroll
    for (int off = 16; off > 0; off >>= 1) local |= __shfl_xor_sync(0xffffffffu, local, off);
    if ((threadIdx.x & 31) == 0 && local) atomicOr(&g_any, local);
}

// ---------------- merged front: degree + weight cvt + MLP1 ----------------
#define WN2 (32*64)
#define WN3 (64*128)
#define WG1 (128*256)
#define WG2 (256*512)
#define WG3P (512*64)
#define WTOT (WN2 + WN3 + WG1 + WG2 + WG3P)

__global__ __launch_bounds__(256) void k_front(
    const void* __restrict__ eidx,
    const float* __restrict__ x,  const float* __restrict__ w1, const float* __restrict__ b1,
    const float* __restrict__ w2, const float* __restrict__ w3,
    const float* __restrict__ g1w, const float* __restrict__ g2w, const float* __restrict__ g3w,
    bf16* __restrict__ h32out)
{
    __shared__ float sw[96];
    __shared__ float sb[32];
    int t   = threadIdx.x;
    int gid = blockIdx.x * 256 + t;
    if (t < 96) sw[t] = w1[t];
    if (t < 32) sb[t] = b1[t];

    // degree count
    for (long long e = gid; e < NEDGES; e += FTHREADS) {
        int d = load_idx(eidx, (long long)NEDGES + e);
        atomicAdd(&g_cnt[d], 1);
    }

    // weight conversion
    for (int j = gid; j < WTOT; j += FTHREADS) {
        int i = j;
        if (i < WN2) { g_wb2[i] = __float2bfloat16(w2[i]); continue; }
        i -= WN2;
        if (i < WN3) { g_wb3[i] = __float2bfloat16(w3[i]); continue; }
        i -= WN3;
        if (i < WG1) { g_wg1[i] = __float2bfloat16(g1w[i]); continue; }
        i -= WG1;
        if (i < WG2) { g_wg2[i] = __float2bfloat16(g2w[i]); continue; }
        i -= WG2;
        int r = i >> 6, c = i & 63;
        g_wg3[i] = __float2bfloat16((c < 50) ? g3w[r * 50 + c] : 0.f);
    }

    // MLP layer 1 (3 -> 32)
    __syncthreads();
    if (gid < NNODES) {
        float x0 = x[gid * 3 + 0], x1 = x[gid * 3 + 1], x2 = x[gid * 3 + 2];
        unsigned pk[16];
        #pragma unroll
        for (int j2 = 0; j2 < 16; j2++) {
            float v0 = fmaxf(fmaf(x0, sw[2*j2],   fmaf(x1, sw[32 + 2*j2],   fmaf(x2, sw[64 + 2*j2],   sb[2*j2]))),   0.f);
            float v1 = fmaxf(fmaf(x0, sw[2*j2+1], fmaf(x1, sw[32 + 2*j2+1], fmaf(x2, sw[64 + 2*j2+1], sb[2*j2+1]))), 0.f);
            __nv_bfloat162 p = __float22bfloat162_rn(make_float2(v0, v1));
            pk[j2] = *(unsigned*)&p;
        }
        uint4* o = (uint4*)(h32out + (long long)gid * 32);
        #pragma unroll
        for (int q = 0; q < 4; q++)
            o[q] = make_uint4(pk[4*q], pk[4*q+1], pk[4*q+2], pk[4*q+3]);
    }
}

// ---------------- scans ----------------
__device__ __forceinline__ int warp_iscan(int v, int lane) {
    #pragma unroll
    for (int off = 1; off < 32; off <<= 1) {
        int u = __shfl_up_sync(0xffffffffu, v, off);
        if (lane >= off) v += u;
    }
    return v;
}

__global__ void k_scan1() {
    __shared__ int wsum[8];
    int t = threadIdx.x, lane = t & 31, w = t >> 5;
    int i = blockIdx.x * 256 + t;
    int v = (i < NNODES) ? g_cnt[i] : 0;
    if (i < NNODES) g_dinv[i] = rsqrtf((float)(v + 1));
    int incl = warp_iscan(v, lane);
    if (lane == 31) wsum[w] = incl;
    __syncthreads();
    if (w == 0) {
        int s = (lane < 8) ? wsum[lane] : 0;
        s = warp_iscan(s, lane);
        if (lane < 8) wsum[lane] = s;
    }
    __syncthreads();
    int woff = (w > 0) ? wsum[w - 1] : 0;
    if (i < NNODES) g_rowptr[i] = woff + incl - v;
    if (t == 255) g_bsum[blockIdx.x] = woff + incl;
}

// merged scan2+scan3: each block redundantly reduces bsum[0..b-1] (L2-hot)
__global__ void k_scan23() {
    __shared__ int red[256];
    int b = blockIdx.x, t = threadIdx.x;
    int partial = 0;
    for (int j = t; j < b; j += 256) partial += g_bsum[j];
    red[t] = partial;
    __syncthreads();
    #pragma unroll
    for (int off = 128; off > 0; off >>= 1) {
        if (t < off) red[t] += red[t + off];
        __syncthreads();
    }
    int s_off = red[0];
    int i = b * 256 + t;
    if (i < NNODES) {
        int rp = g_rowptr[i] + s_off;
        g_rowptr[i] = rp;
        g_ctr[i]    = rp;
    }
    if (b == NBLK - 1 && t == 0) g_rowptr[NNODES] = s_off + g_bsum[b];
}

__global__ void k_bucket(const void* __restrict__ eidx) {
    int e = blockIdx.x * blockDim.x + threadIdx.x;
    if (e >= NEDGES) return;
    int s = load_idx(eidx, e);
    int d = load_idx(eidx, (long long)NEDGES + e);
    int pos = atomicAdd(&g_ctr[d], 1);
    g_csr[pos] = s;
}

// ---------------- cp.async helpers ----------------
__device__ __forceinline__ void cp16(void* dst, const void* src, bool pred) {
    unsigned s = (unsigned)__cvta_generic_to_shared(dst);
    int bytes = pred ? 16 : 0;
    asm volatile("cp.async.cg.shared.global [%0], [%1], 16, %2;\n" :: "r"(s), "l"(src), "r"(bytes));
}
__device__ __forceinline__ void cp_commit() { asm volatile("cp.async.commit_group;\n"); }
template <int N>
__device__ __forceinline__ void cp_wait() { asm volatile("cp.async.wait_group %0;\n" :: "n"(N)); }

// ---------------- bf16 WMMA GEMM, cp.async 3-stage pipeline (dynamic smem) ----------------
#define GBM 128
#define ASTR 40
#define GEMM_STAGE(BNT)  (GBM * ASTR * 2 + 32 * ((BNT) + 8) * 2)
#define GEMM_SMEM(BNT)   (3 * GEMM_STAGE(BNT))

template <int BNT, bool OUTBF>
__global__ __launch_bounds__(256) void k_gemm(
    const bf16* __restrict__ A, const bf16* __restrict__ B, void* __restrict__ Cv,
    int N, int K, int M,
    const float* __restrict__ bias, int do_relu, int dinv_after)
{
    constexpr int BSTR  = BNT + 8;
    constexpr int ABYTES = GBM * ASTR * 2;            // 10240
    constexpr int STAGE  = ABYTES + 32 * BSTR * 2;
    constexpr int CSTR   = BNT + 4;
    constexpr int FN     = BNT / 32;

    extern __shared__ __align__(16) char smem_raw[];

    int tid  = threadIdx.x;
    int warp = tid >> 5;
    int wr = warp >> 1, wc = warp & 1;
    int row0 = blockIdx.y * GBM;
    int col0 = blockIdx.x * BNT;

    wmma::fragment<wmma::accumulator, 16, 16, 16, float> acc[2][FN];
    #pragma unroll
    for (int i = 0; i < 2; i++)
        #pragma unroll
        for (int j = 0; j < FN; j++) wmma::fill_fragment(acc[i][j], 0.f);

    auto loadStage = [&](int k0, int st) {
        bf16* As = (bf16*)(smem_raw + st * STAGE);
        bf16* Bs = (bf16*)(smem_raw + st * STAGE + ABYTES);
        #pragma unroll
        for (int i = 0; i < 2; i++) {
            int id = tid + i * 256;                   // [0, 512)
            int r = id >> 2, c = id & 3;
            int gr = row0 + r;
            bool ok = gr < N;
            const bf16* src = A + (size_t)(ok ? gr : N - 1) * K + k0 + c * 8;
            cp16(As + r * ASTR + c * 8, src, ok);
        }
        constexpr int CPB = BNT / 8;
        #pragma unroll
        for (int i = 0; i < (4 * BNT) / 256; i++) {
            int id = tid + i * 256;
            int r = id / CPB, c = id % CPB;
            cp16(Bs + r * BSTR + c * 8, B + (size_t)(k0 + r) * M + col0 + c * 8, true);
        }
        cp_commit();
    };

    int nk = K >> 5;
    loadStage(0, 0);
    if (nk > 1) loadStage(32, 1);

    for (int kt = 0; kt < nk; kt++) {
        if (kt + 2 < nk)      { loadStage((kt + 2) << 5, (kt + 2) % 3); cp_wait<2>(); }
        else if (kt + 1 < nk) { cp_wait<1>(); }
        else                  { cp_wait<0>(); }
        __syncthreads();

        int st = kt % 3;
        bf16* As = (bf16*)(smem_raw + st * STAGE);
        bf16* Bs = (bf16*)(smem_raw + st * STAGE + ABYTES);
        #pragma unroll
        for (int kk = 0; kk < 32; kk += 16) {
            wmma::fragment<wmma::matrix_a, 16, 16, 16, bf16, wmma::row_major> af[2];
            wmma::fragment<wmma::matrix_b, 16, 16, 16, bf16, wmma::row_major> bfr[FN];
            #pragma unroll
            for (int i = 0; i < 2; i++)
                wmma::load_matrix_sync(af[i], As + (wr * 32 + i * 16) * ASTR + kk, ASTR);
            #pragma unroll
            for (int j = 0; j < FN; j++)
                wmma::load_matrix_sync(bfr[j], Bs + kk * BSTR + wc * (BNT / 2) + j * 16, BSTR);
            #pragma unroll
            for (int i = 0; i < 2; i++)
                #pragma unroll
                for (int j = 0; j < FN; j++)
                    wmma::mma_sync(acc[i][j], af[i], bfr[j], acc[i][j]);
        }
        __syncthreads();   // stage kt%3 gets rewritten by the load issued at iter kt+1
    }

    float* Cs = (float*)smem_raw;
    constexpr int G = BNT / 4;
    #pragma unroll
    for (int ph = 0; ph < 2; ph++) {
        if (wr >= ph * 2 && wr < ph * 2 + 2) {
            #pragma unroll
            for (int i = 0; i < 2; i++)
                #pragma unroll
                for (int j = 0; j < FN; j++)
                    wmma::store_matrix_sync(
                        Cs + (size_t)(wr * 32 - ph * 64 + i * 16) * CSTR + wc * (BNT / 2) + j * 16,
                        acc[i][j], CSTR, wmma::mem_row_major);
        }
        __syncthreads();
        #pragma unroll
        for (int i = 0; i < (64 * G) / 256; i++) {
            int id = tid + i * 256;
            int r = id / G, c4 = id % G;
            int gr = row0 + ph * 64 + r;
            if (gr < N) {
                float* s = Cs + (size_t)r * CSTR + c4 * 4;
                float4 v = make_float4(s[0], s[1], s[2], s[3]);
                if (bias) {
                    const float* bb = bias + col0 + c4 * 4;
                    v.x += bb[0]; v.y += bb[1]; v.z += bb[2]; v.w += bb[3];
                }
                if (do_relu) {
                    v.x = fmaxf(v.x, 0.f); v.y = fmaxf(v.y, 0.f);
                    v.z = fmaxf(v.z, 0.f); v.w = fmaxf(v.w, 0.f);
                }
                if (dinv_after) {
                    float d = g_dinv[gr];
                    v.x *= d; v.y *= d; v.z *= d; v.w *= d;
                }
                if (OUTBF) {
                    __nv_bfloat162 p0 = __float22bfloat162_rn(make_float2(v.x, v.y));
                    __nv_bfloat162 p1 = __float22bfloat162_rn(make_float2(v.z, v.w));
                    uint2 pk = make_uint2(*(unsigned*)&p0, *(unsigned*)&p1);
                    *(uint2*)((bf16*)Cv + (size_t)gr * M + col0 + c4 * 4) = pk;
                } else {
                    *(float4*)((float*)Cv + (size_t)gr * M + col0 + c4 * 4) = v;
                }
            }
        }
        __syncthreads();
    }
}

// ---------------- bf16 aggregation, 16-edge unroll, optional per-source dinv ----------------
template <int F, bool SSRC>
__global__ __launch_bounds__(256) void k_agg(
    const bf16* __restrict__ ts, bf16* __restrict__ out)
{
    constexpr int VEC = F / 32;
    int lane = threadIdx.x & 31;
    int node = blockIdx.x * 8 + (threadIdx.x >> 5);
    if (node >= NNODES) return;

    float di = g_dinv[node];
    float dself = SSRC ? di : 1.f;

    float acc[VEC];
    const bf16* self = ts + (size_t)node * F + lane * VEC;
    #pragma unroll
    for (int p = 0; p < VEC / 2; p++) {
        float2 f = __bfloat1622float2(*(const __nv_bfloat162*)(self + 2 * p));
        acc[2*p] = f.x * dself; acc[2*p+1] = f.y * dself;
    }

    auto addRow = [&](int s) {
        float ds = SSRC ? g_dinv[s] : 1.f;
        const bf16* row = ts + (size_t)s * F + lane * VEC;
        if (VEC == 4) {
            uint2 v = *(const uint2*)row;
            float2 f0 = __bfloat1622float2(*(__nv_bfloat162*)&v.x);
            float2 f1 = __bfloat1622float2(*(__nv_bfloat162*)&v.y);
            if (SSRC) {
                acc[0] = fmaf(f0.x, ds, acc[0]); acc[1] = fmaf(f0.y, ds, acc[1]);
                acc[2] = fmaf(f1.x, ds, acc[2]); acc[3] = fmaf(f1.y, ds, acc[3]);
            } else {
                acc[0] += f0.x; acc[1] += f0.y; acc[2] += f1.x; acc[3] += f1.y;
            }
        } else {
            uint4 v = *(const uint4*)row;
            float2 f0 = __bfloat1622float2(*(__nv_bfloat162*)&v.x);
            float2 f1 = __bfloat1622float2(*(__nv_bfloat162*)&v.y);
            float2 f2 = __bfloat1622float2(*(__nv_bfloat162*)&v.z);
            float2 f3 = __bfloat1622float2(*(__nv_bfloat162*)&v.w);
            if (SSRC) {
                acc[0] = fmaf(f0.x, ds, acc[0]); acc[1] = fmaf(f0.y, ds, acc[1]);
                acc[2] = fmaf(f1.x, ds, acc[2]); acc[3] = fmaf(f1.y, ds, acc[3]);
                acc[4] = fmaf(f2.x, ds, acc[4]); acc[5] = fmaf(f2.y, ds, acc[5]);
                acc[6] = fmaf(f3.x, ds, acc[6]); acc[7] = fmaf(f3.y, ds, acc[7]);
            } else {
                acc[0] += f0.x; acc[1] += f0.y; acc[2] += f1.x; acc[3] += f1.y;
                acc[4] += f2.x; acc[5] += f2.y; acc[6] += f3.x; acc[7] += f3.y;
            }
        }
    };

    int e = g_rowptr[node], end = g_rowptr[node + 1];
    for (; e + 16 <= end; e += 16) {
        int s[16];
        #pragma unroll
        for (int j = 0; j < 16; j++) s[j] = g_csr[e + j];
        #pragma unroll
        for (int j = 0; j < 16; j++) addRow(s[j]);
    }
    for (; e + 4 <= end; e += 4) {
        int s[4];
        #pragma unroll
        for (int j = 0; j < 4; j++) s[j] = g_csr[e + j];
        #pragma unroll
        for (int j = 0; j < 4; j++) addRow(s[j]);
    }
    for (; e < end; e++) addRow(g_csr[e]);

    bf16* o = out + (size_t)node * F + lane * VEC;
    #pragma unroll
    for (int p = 0; p < VEC / 2; p++) {
        __nv_bfloat162 pk = __float22bfloat162_rn(make_float2(acc[2*p] * di, acc[2*p+1] * di));
        *(__nv_bfloat162*)(o + 2 * p) = pk;
    }
}

// ---------------- final aggregation + softmax: warp per node ----------------
__global__ __launch_bounds__(256) void k_agg_softmax(
    const float* __restrict__ ts, float* __restrict__ out, const float* __restrict__ bias)
{
    int lane = threadIdx.x & 31;
    int node = blockIdx.x * 8 + (threadIdx.x >> 5);
    if (node >= NNODES) return;

    const float2* tsv = (const float2*)ts;          // 32 float2 per row
    float2 acc = tsv[(size_t)node * 32 + lane];     // self
    int e = g_rowptr[node], end = g_rowptr[node + 1];
    for (; e + 16 <= end; e += 16) {
        int s[16];
        #pragma unroll
        for (int j = 0; j < 16; j++) s[j] = g_csr[e + j];
        #pragma unroll
        for (int j = 0; j < 16; j++) {
            float2 v = tsv[(size_t)s[j] * 32 + lane];
            acc.x += v.x; acc.y += v.y;
        }
    }
    for (; e < end; e++) {
        float2 v = tsv[(size_t)g_csr[e] * 32 + lane];
        acc.x += v.x; acc.y += v.y;
    }

    float di = g_dinv[node];
    float vx = -INFINITY, vy = -INFINITY;
    if (lane < 25) {
        const float2 bb = *(const float2*)(bias + 2 * lane);
        vx = fmaf(di, acc.x, bb.x);
        vy = fmaf(di, acc.y, bb.y);
    }
    float m = fmaxf(vx, vy);
    #pragma unroll
    for (int off = 16; off > 0; off >>= 1) m = fmaxf(m, __shfl_xor_sync(0xffffffffu, m, off));
    float ex = (lane < 25) ? expf(vx - m) : 0.f;
    float ey = (lane < 25) ? expf(vy - m) : 0.f;
    float ssum = ex + ey;
    #pragma unroll
    for (int off = 16; off > 0; off >>= 1) ssum += __shfl_xor_sync(0xffffffffu, ssum, off);
    if (lane < 25) {
        float inv = 1.f / ssum;
        *(float2*)(out + (size_t)node * 50 + 2 * lane) = make_float2(ex * inv, ey * inv);
    }
}

// ---------------- launch ----------------
extern "C" void kernel_launch(void* const* d_in, const int* in_sizes, int n_in,
                              void* d_out, int out_size)
{
    const float* x    = (const float*)d_in[0];
    const void*  eidx = d_in[1];
    const float* w1 = (const float*)d_in[2],  *b1 = (const float*)d_in[3];
    const float* w2 = (const float*)d_in[4];
    const float* b2 = (const float*)d_in[5];
    const float* w3 = (const float*)d_in[6],  *b3 = (const float*)d_in[7];
    const float* g1w = (const float*)d_in[8],  *g1b = (const float*)d_in[9];
    const float* g2w = (const float*)d_in[10], *g2b = (const float*)d_in[11];
    const float* g3w = (const float*)d_in[12], *g3b = (const float*)d_in[13];
    float* out = (float*)d_out;

    bf16 *h32b, *h64b, *h128b, *u128, *a256, *u256, *a512;
    bf16 *wb2, *wb3, *wg1, *wg2, *wg3;
    float *t50;
    cudaGetSymbolAddress((void**)&h32b,  g_h32b);
    cudaGetSymbolAddress((void**)&h64b,  g_h64b);
    cudaGetSymbolAddress((void**)&h128b, g_h128b);
    cudaGetSymbolAddress((void**)&u128,  g_u128);
    cudaGetSymbolAddress((void**)&a256,  g_a256);
    cudaGetSymbolAddress((void**)&u256,  g_u256);
    cudaGetSymbolAddress((void**)&a512,  g_a512);
    cudaGetSymbolAddress((void**)&t50,   g_t50);
    cudaGetSymbolAddress((void**)&wb2,   g_wb2);
    cudaGetSymbolAddress((void**)&wb3,   g_wb3);
    cudaGetSymbolAddress((void**)&wg1,   g_wg1);
    cudaGetSymbolAddress((void**)&wg2,   g_wg2);
    cudaGetSymbolAddress((void**)&wg3,   g_wg3);

    const int N = NNODES;
    const int NROWB = (N + GBM - 1) / GBM;   // 391
    const int NAGGB = (N + 7) / 8;           // 6250
    const int S128 = GEMM_SMEM(128);         // 56832
    const int S64  = GEMM_SMEM(64);          // 44544

    // one-time setup (first call = correctness run, outside capture)
    static cudaStream_t s2 = nullptr;
    static cudaEvent_t  e0 = nullptr, e1 = nullptr;
    if (!s2) {
        cudaStreamCreateWithFlags(&s2, cudaStreamNonBlocking);
        cudaEventCreateWithFlags(&e0, cudaEventDisableTiming);
        cudaEventCreateWithFlags(&e1, cudaEventDisableTiming);
        cudaFuncSetAttribute(k_gemm<128, true>,  cudaFuncAttributeMaxDynamicSharedMemorySize, S128);
        cudaFuncSetAttribute(k_gemm<64,  true>,  cudaFuncAttributeMaxDynamicSharedMemorySize, S64);
        cudaFuncSetAttribute(k_gemm<64,  false>, cudaFuncAttributeMaxDynamicSharedMemorySize, S64);
    }

    // detect dtype + zero counters (must precede front's degree atomics)
    k_detect<<<NBLK, 256>>>((const unsigned*)eidx);

    // front: degree + weight cvt + MLP1
    k_front<<<NBLK, 256>>>(eidx, x, w1, b1, w2, w3, g1w, g2w, g3w, h32b);

    // fork: MLP GEMM chain on s2 (independent of CSR build; no dinv needed)
    cudaEventRecord(e0, 0);
    cudaStreamWaitEvent(s2, e0, 0);
    k_gemm< 64, true><<<dim3(1, NROWB), 256, S64,  s2>>>(h32b, wb2, h64b,  N, 32,  64,  b2, 1, 0);
    k_gemm<128, true><<<dim3(1, NROWB), 256, S128, s2>>>(h64b, wb3, h128b, N, 64,  128, b3, 1, 0);
    cudaEventRecord(e1, s2);

    // CSR chain on main stream
    k_scan1<<<NBLK, 256>>>();                      // also computes dinv
    k_scan23<<<NBLK, 256>>>();
    k_bucket<<<(NEDGES + 255) / 256, 256>>>(eidx);

    // join
    cudaStreamWaitEvent(0, e1, 0);

    // GCN 1: aggregate inputs (scaling sources by dinv), then GEMM bias+relu+dinv
    k_agg<128, true><<<NAGGB, 256>>>(h128b, u128);
    k_gemm<128, true><<<dim3(2, NROWB), 256, S128>>>(u128, wg1, a256, N, 128, 256, g1b, 1, 1);

    // GCN 2
    k_agg<256, false><<<NAGGB, 256>>>(a256, u256);
    k_gemm<128, true><<<dim3(4, NROWB), 256, S128>>>(u256, wg2, a512, N, 256, 512, g2b, 1, 1);

    // GCN 3: GEMM first (narrow output), aggregate after + softmax
    k_gemm<64, false><<<dim3(1, NROWB), 256, S64>>>(a512, wg3, t50, N, 512, 64, nullptr, 0, 0);
    k_agg_softmax<<<NAGGB, 256>>>(t50, out, g3b);
}

// round 14
// speedup vs baseline: 1.0102x; 1.0102x over previous
#include <cuda_runtime.h>
#include <cuda_bf16.h>
#include <mma.h>
#include <math.h>

using namespace nvcuda;
typedef __nv_bfloat16 bf16;

// ---------------- problem constants ----------------
#define NNODES 50000
#define NEDGES 800000
#define NBLK   ((NNODES + 255) / 256)   // 196

// ---------------- device scratch ----------------
__device__ unsigned g_any;
__device__ int   g_cnt[NNODES];
__device__ int   g_rowptr[NNODES + 1];
__device__ int   g_ctr[NNODES];
__device__ int   g_csr[NEDGES];
__device__ float g_dinv[NNODES];
__device__ int   g_bsum[NBLK];

__device__ bf16  g_h32b [NNODES * 32];
__device__ bf16  g_h64b [NNODES * 64];
__device__ bf16  g_h128b[NNODES * 128];   // relu(mlp3)  (NO dinv — applied in agg)
__device__ bf16  g_u128 [NNODES * 128];   // aggregated
__device__ bf16  g_a256 [NNODES * 256];   // relu(gcn1) * dinv
__device__ bf16  g_u256 [NNODES * 256];
__device__ bf16  g_a512 [NNODES * 512];   // relu(gcn2) * dinv
__device__ float g_t50  [NNODES * 64];    // padded, pre-agg logits

__device__ bf16  g_wb2[32 * 64];
__device__ bf16  g_wb3[64 * 128];
__device__ bf16  g_wg1[128 * 256];
__device__ bf16  g_wg2[256 * 512];
__device__ bf16  g_wg3[512 * 64];         // zero-padded 50 -> 64

// ---------------- edge-index dtype handling ----------------
__device__ __forceinline__ int load_idx(const void* p, long long e) {
    if (g_any == 0u) return (int)((const long long*)p)[e];   // int64 data
    return ((const int*)p)[e];
}

#define FTHREADS (NBLK * 256)   // 50176

// ---------------- detect + zero counters (must precede k_front's atomics) ----------------
__global__ void k_detect(const unsigned* __restrict__ e32) {
    int gid = blockIdx.x * 256 + threadIdx.x;
    if (gid < NNODES) g_cnt[gid] = 0;
    unsigned local = (gid < 16384) ? e32[2 * gid + 1] : 0u;
    #pragma unroll
    for (int off = 16; off > 0; off >>= 1) local |= __shfl_xor_sync(0xffffffffu, local, off);
    if ((threadIdx.x & 31) == 0 && local) atomicOr(&g_any, local);
}

// ---------------- merged front: degree + weight cvt + MLP1 ----------------
#define WN2 (32*64)
#define WN3 (64*128)
#define WG1 (128*256)
#define WG2 (256*512)
#define WG3P (512*64)
#define WTOT (WN2 + WN3 + WG1 + WG2 + WG3P)

__global__ __launch_bounds__(256) void k_front(
    const void* __restrict__ eidx,
    const float* __restrict__ x,  const float* __restrict__ w1, const float* __restrict__ b1,
    const float* __restrict__ w2, const float* __restrict__ w3,
    const float* __restrict__ g1w, const float* __restrict__ g2w, const float* __restrict__ g3w,
    bf16* __restrict__ h32out)
{
    __shared__ float sw[96];
    __shared__ float sb[32];
    int t   = threadIdx.x;
    int gid = blockIdx.x * 256 + t;
    if (t < 96) sw[t] = w1[t];
    if (t < 32) sb[t] = b1[t];

    // degree count
    for (long long e = gid; e < NEDGES; e += FTHREADS) {
        int d = load_idx(eidx, (long long)NEDGES + e);
        atomicAdd(&g_cnt[d], 1);
    }

    // weight conversion
    for (int j = gid; j < WTOT; j += FTHREADS) {
        int i = j;
        if (i < WN2) { g_wb2[i] = __float2bfloat16(w2[i]); continue; }
        i -= WN2;
        if (i < WN3) { g_wb3[i] = __float2bfloat16(w3[i]); continue; }
        i -= WN3;
        if (i < WG1) { g_wg1[i] = __float2bfloat16(g1w[i]); continue; }
        i -= WG1;
        if (i < WG2) { g_wg2[i] = __float2bfloat16(g2w[i]); continue; }
        i -= WG2;
        int r = i >> 6, c = i & 63;
        g_wg3[i] = __float2bfloat16((c < 50) ? g3w[r * 50 + c] : 0.f);
    }

    // MLP layer 1 (3 -> 32)
    __syncthreads();
    if (gid < NNODES) {
        float x0 = x[gid * 3 + 0], x1 = x[gid * 3 + 1], x2 = x[gid * 3 + 2];
        unsigned pk[16];
        #pragma unroll
        for (int j2 = 0; j2 < 16; j2++) {
            float v0 = fmaxf(fmaf(x0, sw[2*j2],   fmaf(x1, sw[32 + 2*j2],   fmaf(x2, sw[64 + 2*j2],   sb[2*j2]))),   0.f);
            float v1 = fmaxf(fmaf(x0, sw[2*j2+1], fmaf(x1, sw[32 + 2*j2+1], fmaf(x2, sw[64 + 2*j2+1], sb[2*j2+1]))), 0.f);
            __nv_bfloat162 p = __float22bfloat162_rn(make_float2(v0, v1));
            pk[j2] = *(unsigned*)&p;
        }
        uint4* o = (uint4*)(h32out + (long long)gid * 32);
        #pragma unroll
        for (int q = 0; q < 4; q++)
            o[q] = make_uint4(pk[4*q], pk[4*q+1], pk[4*q+2], pk[4*q+3]);
    }
}

// ---------------- scans ----------------
__device__ __forceinline__ int warp_iscan(int v, int lane) {
    #pragma unroll
    for (int off = 1; off < 32; off <<= 1) {
        int u = __shfl_up_sync(0xffffffffu, v, off);
        if (lane >= off) v += u;
    }
    return v;
}

__global__ void k_scan1() {
    __shared__ int wsum[8];
    int t = threadIdx.x, lane = t & 31, w = t >> 5;
    int i = blockIdx.x * 256 + t;
    int v = (i < NNODES) ? g_cnt[i] : 0;
    if (i < NNODES) g_dinv[i] = rsqrtf((float)(v + 1));
    int incl = warp_iscan(v, lane);
    if (lane == 31) wsum[w] = incl;
    __syncthreads();
    if (w == 0) {
        int s = (lane < 8) ? wsum[lane] : 0;
        s = warp_iscan(s, lane);
        if (lane < 8) wsum[lane] = s;
    }
    __syncthreads();
    int woff = (w > 0) ? wsum[w - 1] : 0;
    if (i < NNODES) g_rowptr[i] = woff + incl - v;
    if (t == 255) g_bsum[blockIdx.x] = woff + incl;
}

// merged scan2+scan3: each block redundantly reduces bsum[0..b-1] (L2-hot)
__global__ void k_scan23() {
    __shared__ int red[256];
    int b = blockIdx.x, t = threadIdx.x;
    int partial = 0;
    for (int j = t; j < b; j += 256) partial += g_bsum[j];
    red[t] = partial;
    __syncthreads();
    #pragma unroll
    for (int off = 128; off > 0; off >>= 1) {
        if (t < off) red[t] += red[t + off];
        __syncthreads();
    }
    int s_off = red[0];
    int i = b * 256 + t;
    if (i < NNODES) {
        int rp = g_rowptr[i] + s_off;
        g_rowptr[i] = rp;
        g_ctr[i]    = rp;
    }
    if (b == NBLK - 1 && t == 0) g_rowptr[NNODES] = s_off + g_bsum[b];
}

__global__ void k_bucket(const void* __restrict__ eidx) {
    int e = blockIdx.x * blockDim.x + threadIdx.x;
    if (e >= NEDGES) return;
    int s = load_idx(eidx, e);
    int d = load_idx(eidx, (long long)NEDGES + e);
    int pos = atomicAdd(&g_ctr[d], 1);
    g_csr[pos] = s;
}

// ---------------- cp.async helpers ----------------
__device__ __forceinline__ void cp16(void* dst, const void* src, bool pred) {
    unsigned s = (unsigned)__cvta_generic_to_shared(dst);
    int bytes = pred ? 16 : 0;
    asm volatile("cp.async.cg.shared.global [%0], [%1], 16, %2;\n" :: "r"(s), "l"(src), "r"(bytes));
}
__device__ __forceinline__ void cp_commit() { asm volatile("cp.async.commit_group;\n"); }
template <int N>
__device__ __forceinline__ void cp_wait() { asm volatile("cp.async.wait_group %0;\n" :: "n"(N)); }

// ---------------- bf16 WMMA GEMM, cp.async double-buffered (R10 proven config) ----------------
#define GBM 128
#define ASTR 40

template <int BNT, bool OUTBF>
__global__ __launch_bounds__(256) void k_gemm(
    const bf16* __restrict__ A, const bf16* __restrict__ B, void* __restrict__ Cv,
    int N, int K, int M,
    const float* __restrict__ bias, int do_relu, int dinv_after)
{
    constexpr int BSTR  = BNT + 8;
    constexpr int ABYTES = GBM * ASTR * 2;            // 10240
    constexpr int STAGE  = ABYTES + 32 * BSTR * 2;
    constexpr int CSTR   = BNT + 4;
    constexpr int FN     = BNT / 32;

    __shared__ __align__(16) char smem_raw[2 * STAGE];

    int tid  = threadIdx.x;
    int warp = tid >> 5;
    int wr = warp >> 1, wc = warp & 1;
    int row0 = blockIdx.y * GBM;
    int col0 = blockIdx.x * BNT;

    wmma::fragment<wmma::accumulator, 16, 16, 16, float> acc[2][FN];
    #pragma unroll
    for (int i = 0; i < 2; i++)
        #pragma unroll
        for (int j = 0; j < FN; j++) wmma::fill_fragment(acc[i][j], 0.f);

    auto loadStage = [&](int k0, int st) {
        bf16* As = (bf16*)(smem_raw + st * STAGE);
        bf16* Bs = (bf16*)(smem_raw + st * STAGE + ABYTES);
        #pragma unroll
        for (int i = 0; i < 2; i++) {
            int id = tid + i * 256;                   // [0, 512)
            int r = id >> 2, c = id & 3;
            int gr = row0 + r;
            bool ok = gr < N;
            const bf16* src = A + (size_t)(ok ? gr : N - 1) * K + k0 + c * 8;
            cp16(As + r * ASTR + c * 8, src, ok);
        }
        constexpr int CPB = BNT / 8;
        #pragma unroll
        for (int i = 0; i < (4 * BNT) / 256; i++) {
            int id = tid + i * 256;
            int r = id / CPB, c = id % CPB;
            cp16(Bs + r * BSTR + c * 8, B + (size_t)(k0 + r) * M + col0 + c * 8, true);
        }
        cp_commit();
    };

    int nk = K >> 5;
    loadStage(0, 0);

    for (int kt = 0; kt < nk; kt++) {
        if (kt + 1 < nk) { loadStage((kt + 1) << 5, (kt + 1) & 1); cp_wait<1>(); }
        else             { cp_wait<0>(); }
        __syncthreads();

        bf16* As = (bf16*)(smem_raw + (kt & 1) * STAGE);
        bf16* Bs = (bf16*)(smem_raw + (kt & 1) * STAGE + ABYTES);
        #pragma unroll
        for (int kk = 0; kk < 32; kk += 16) {
            wmma::fragment<wmma::matrix_a, 16, 16, 16, bf16, wmma::row_major> af[2];
            wmma::fragment<wmma::matrix_b, 16, 16, 16, bf16, wmma::row_major> bfr[FN];
            #pragma unroll
            for (int i = 0; i < 2; i++)
                wmma::load_matrix_sync(af[i], As + (wr * 32 + i * 16) * ASTR + kk, ASTR);
            #pragma unroll
            for (int j = 0; j < FN; j++)
                wmma::load_matrix_sync(bfr[j], Bs + kk * BSTR + wc * (BNT / 2) + j * 16, BSTR);
            #pragma unroll
            for (int i = 0; i < 2; i++)
                #pragma unroll
                for (int j = 0; j < FN; j++)
                    wmma::mma_sync(acc[i][j], af[i], bfr[j], acc[i][j]);
        }
        __syncthreads();
    }

    float* Cs = (float*)smem_raw;
    constexpr int G = BNT / 4;
    #pragma unroll
    for (int ph = 0; ph < 2; ph++) {
        if (wr >= ph * 2 && wr < ph * 2 + 2) {
            #pragma unroll
            for (int i = 0; i < 2; i++)
                #pragma unroll
                for (int j = 0; j < FN; j++)
                    wmma::store_matrix_sync(
                        Cs + (size_t)(wr * 32 - ph * 64 + i * 16) * CSTR + wc * (BNT / 2) + j * 16,
                        acc[i][j], CSTR, wmma::mem_row_major);
        }
        __syncthreads();
        #pragma unroll
        for (int i = 0; i < (64 * G) / 256; i++) {
            int id = tid + i * 256;
            int r = id / G, c4 = id % G;
            int gr = row0 + ph * 64 + r;
            if (gr < N) {
                float* s = Cs + (size_t)r * CSTR + c4 * 4;
                float4 v = make_float4(s[0], s[1], s[2], s[3]);
                if (bias) {
                    const float* bb = bias + col0 + c4 * 4;
                    v.x += bb[0]; v.y += bb[1]; v.z += bb[2]; v.w += bb[3];
                }
                if (do_relu) {
                    v.x = fmaxf(v.x, 0.f); v.y = fmaxf(v.y, 0.f);
                    v.z = fmaxf(v.z, 0.f); v.w = fmaxf(v.w, 0.f);
                }
                if (dinv_after) {
                    float d = g_dinv[gr];
                    v.x *= d; v.y *= d; v.z *= d; v.w *= d;
                }
                if (OUTBF) {
                    __nv_bfloat162 p0 = __float22bfloat162_rn(make_float2(v.x, v.y));
                    __nv_bfloat162 p1 = __float22bfloat162_rn(make_float2(v.z, v.w));
                    uint2 pk = make_uint2(*(unsigned*)&p0, *(unsigned*)&p1);
                    *(uint2*)((bf16*)Cv + (size_t)gr * M + col0 + c4 * 4) = pk;
                } else {
                    *(float4*)((float*)Cv + (size_t)gr * M + col0 + c4 * 4) = v;
                }
            }
        }
        __syncthreads();
    }
}

// ---------------- F=128 aggregation: half-warp (16 lanes x 16B) per node, source dinv ----------------
__global__ __launch_bounds__(256) void k_agg128(
    const bf16* __restrict__ ts, bf16* __restrict__ out)
{
    int lane16 = threadIdx.x & 15;
    int node = blockIdx.x * 16 + (threadIdx.x >> 4);
    if (node >= NNODES) return;

    float di = g_dinv[node];
    float acc[8];
    {
        uint4 v = *(const uint4*)(ts + (size_t)node * 128 + lane16 * 8);
        float2 f0 = __bfloat1622float2(*(__nv_bfloat162*)&v.x);
        float2 f1 = __bfloat1622float2(*(__nv_bfloat162*)&v.y);
        float2 f2 = __bfloat1622float2(*(__nv_bfloat162*)&v.z);
        float2 f3 = __bfloat1622float2(*(__nv_bfloat162*)&v.w);
        acc[0] = f0.x * di; acc[1] = f0.y * di; acc[2] = f1.x * di; acc[3] = f1.y * di;
        acc[4] = f2.x * di; acc[5] = f2.y * di; acc[6] = f3.x * di; acc[7] = f3.y * di;
    }

    auto addRow = [&](int s) {
        float ds = g_dinv[s];
        uint4 v = *(const uint4*)(ts + (size_t)s * 128 + lane16 * 8);
        float2 f0 = __bfloat1622float2(*(__nv_bfloat162*)&v.x);
        float2 f1 = __bfloat1622float2(*(__nv_bfloat162*)&v.y);
        float2 f2 = __bfloat1622float2(*(__nv_bfloat162*)&v.z);
        float2 f3 = __bfloat1622float2(*(__nv_bfloat162*)&v.w);
        acc[0] = fmaf(f0.x, ds, acc[0]); acc[1] = fmaf(f0.y, ds, acc[1]);
        acc[2] = fmaf(f1.x, ds, acc[2]); acc[3] = fmaf(f1.y, ds, acc[3]);
        acc[4] = fmaf(f2.x, ds, acc[4]); acc[5] = fmaf(f2.y, ds, acc[5]);
        acc[6] = fmaf(f3.x, ds, acc[6]); acc[7] = fmaf(f3.y, ds, acc[7]);
    };

    int e = g_rowptr[node], end = g_rowptr[node + 1];
    for (; e + 8 <= end; e += 8) {
        int s[8];
        #pragma unroll
        for (int j = 0; j < 8; j++) s[j] = g_csr[e + j];
        #pragma unroll
        for (int j = 0; j < 8; j++) addRow(s[j]);
    }
    for (; e < end; e++) addRow(g_csr[e]);

    bf16* o = out + (size_t)node * 128 + lane16 * 8;
    #pragma unroll
    for (int p = 0; p < 4; p++) {
        __nv_bfloat162 pk = __float22bfloat162_rn(make_float2(acc[2*p] * di, acc[2*p+1] * di));
        *(__nv_bfloat162*)(o + 2 * p) = pk;
    }
}

// ---------------- F=256 aggregation: warp per node (pre-scaled input) ----------------
__global__ __launch_bounds__(256) void k_agg256(
    const bf16* __restrict__ ts, bf16* __restrict__ out)
{
    int lane = threadIdx.x & 31;
    int node = blockIdx.x * 8 + (threadIdx.x >> 5);
    if (node >= NNODES) return;

    float acc[8];
    {
        uint4 v = *(const uint4*)(ts + (size_t)node * 256 + lane * 8);
        float2 f0 = __bfloat1622float2(*(__nv_bfloat162*)&v.x);
        float2 f1 = __bfloat1622float2(*(__nv_bfloat162*)&v.y);
        float2 f2 = __bfloat1622float2(*(__nv_bfloat162*)&v.z);
        float2 f3 = __bfloat1622float2(*(__nv_bfloat162*)&v.w);
        acc[0] = f0.x; acc[1] = f0.y; acc[2] = f1.x; acc[3] = f1.y;
        acc[4] = f2.x; acc[5] = f2.y; acc[6] = f3.x; acc[7] = f3.y;
    }

    auto addRow = [&](int s) {
        uint4 v = *(const uint4*)(ts + (size_t)s * 256 + lane * 8);
        float2 f0 = __bfloat1622float2(*(__nv_bfloat162*)&v.x);
        float2 f1 = __bfloat1622float2(*(__nv_bfloat162*)&v.y);
        float2 f2 = __bfloat1622float2(*(__nv_bfloat162*)&v.z);
        float2 f3 = __bfloat1622float2(*(__nv_bfloat162*)&v.w);
        acc[0] += f0.x; acc[1] += f0.y; acc[2] += f1.x; acc[3] += f1.y;
        acc[4] += f2.x; acc[5] += f2.y; acc[6] += f3.x; acc[7] += f3.y;
    };

    int e = g_rowptr[node], end = g_rowptr[node + 1];
    for (; e + 8 <= end; e += 8) {
        int s[8];
        #pragma unroll
        for (int j = 0; j < 8; j++) s[j] = g_csr[e + j];
        #pragma unroll
        for (int j = 0; j < 8; j++) addRow(s[j]);
    }
    for (; e + 4 <= end; e += 4) {
        int s[4];
        #pragma unroll
        for (int j = 0; j < 4; j++) s[j] = g_csr[e + j];
        #pragma unroll
        for (int j = 0; j < 4; j++) addRow(s[j]);
    }
    for (; e < end; e++) addRow(g_csr[e]);

    float di = g_dinv[node];
    bf16* o = out + (size_t)node * 256 + lane * 8;
    #pragma unroll
    for (int p = 0; p < 4; p++) {
        __nv_bfloat162 pk = __float22bfloat162_rn(make_float2(acc[2*p] * di, acc[2*p+1] * di));
        *(__nv_bfloat162*)(o + 2 * p) = pk;
    }
}

// ---------------- final aggregation + softmax: warp per node ----------------
__global__ __launch_bounds__(256) void k_agg_softmax(
    const float* __restrict__ ts, float* __restrict__ out, const float* __restrict__ bias)
{
    int lane = threadIdx.x & 31;
    int node = blockIdx.x * 8 + (threadIdx.x >> 5);
    if (node >= NNODES) return;

    const float2* tsv = (const float2*)ts;          // 32 float2 per row
    float2 acc = tsv[(size_t)node * 32 + lane];     // self
    int e = g_rowptr[node], end = g_rowptr[node + 1];
    for (; e + 8 <= end; e += 8) {
        int s[8];
        #pragma unroll
        for (int j = 0; j < 8; j++) s[j] = g_csr[e + j];
        #pragma unroll
        for (int j = 0; j < 8; j++) {
            float2 v = tsv[(size_t)s[j] * 32 + lane];
            acc.x += v.x; acc.y += v.y;
        }
    }
    for (; e < end; e++) {
        float2 v = tsv[(size_t)g_csr[e] * 32 + lane];
        acc.x += v.x; acc.y += v.y;
    }

    float di = g_dinv[node];
    float vx = -INFINITY, vy = -INFINITY;
    if (lane < 25) {
        const float2 bb = *(const float2*)(bias + 2 * lane);
        vx = fmaf(di, acc.x, bb.x);
        vy = fmaf(di, acc.y, bb.y);
    }
    float m = fmaxf(vx, vy);
    #pragma unroll
    for (int off = 16; off > 0; off >>= 1) m = fmaxf(m, __shfl_xor_sync(0xffffffffu, m, off));
    float ex = (lane < 25) ? expf(vx - m) : 0.f;
    float ey = (lane < 25) ? expf(vy - m) : 0.f;
    float ssum = ex + ey;
    #pragma unroll
    for (int off = 16; off > 0; off >>= 1) ssum += __shfl_xor_sync(0xffffffffu, ssum, off);
    if (lane < 25) {
        float inv = 1.f / ssum;
        *(float2*)(out + (size_t)node * 50 + 2 * lane) = make_float2(ex * inv, ey * inv);
    }
}

// ---------------- launch ----------------
extern "C" void kernel_launch(void* const* d_in, const int* in_sizes, int n_in,
                              void* d_out, int out_size)
{
    const float* x    = (const float*)d_in[0];
    const void*  eidx = d_in[1];
    const float* w1 = (const float*)d_in[2],  *b1 = (const float*)d_in[3];
    const float* w2 = (const float*)d_in[4];
    const float* b2 = (const float*)d_in[5];
    const float* w3 = (const float*)d_in[6],  *b3 = (const float*)d_in[7];
    const float* g1w = (const float*)d_in[8],  *g1b = (const float*)d_in[9];
    const float* g2w = (const float*)d_in[10], *g2b = (const float*)d_in[11];
    const float* g3w = (const float*)d_in[12], *g3b = (const float*)d_in[13];
    float* out = (float*)d_out;

    bf16 *h32b, *h64b, *h128b, *u128, *a256, *u256, *a512;
    bf16 *wb2, *wb3, *wg1, *wg2, *wg3;
    float *t50;
    cudaGetSymbolAddress((void**)&h32b,  g_h32b);
    cudaGetSymbolAddress((void**)&h64b,  g_h64b);
    cudaGetSymbolAddress((void**)&h128b, g_h128b);
    cudaGetSymbolAddress((void**)&u128,  g_u128);
    cudaGetSymbolAddress((void**)&a256,  g_a256);
    cudaGetSymbolAddress((void**)&u256,  g_u256);
    cudaGetSymbolAddress((void**)&a512,  g_a512);
    cudaGetSymbolAddress((void**)&t50,   g_t50);
    cudaGetSymbolAddress((void**)&wb2,   g_wb2);
    cudaGetSymbolAddress((void**)&wb3,   g_wb3);
    cudaGetSymbolAddress((void**)&wg1,   g_wg1);
    cudaGetSymbolAddress((void**)&wg2,   g_wg2);
    cudaGetSymbolAddress((void**)&wg3,   g_wg3);

    const int N = NNODES;
    const int NROWB = (N + GBM - 1) / GBM;   // 391
    const int NAGGB = (N + 7) / 8;           // 6250

    // one-time setup (first call = correctness run, outside capture)
    static cudaStream_t s2 = nullptr;
    static cudaEvent_t  e0 = nullptr, e1 = nullptr;
    if (!s2) {
        cudaStreamCreateWithFlags(&s2, cudaStreamNonBlocking);
        cudaEventCreateWithFlags(&e0, cudaEventDisableTiming);
        cudaEventCreateWithFlags(&e1, cudaEventDisableTiming);
    }

    // detect dtype + zero counters (must precede front's degree atomics)
    k_detect<<<NBLK, 256>>>((const unsigned*)eidx);

    // front: degree + weight cvt + MLP1
    k_front<<<NBLK, 256>>>(eidx, x, w1, b1, w2, w3, g1w, g2w, g3w, h32b);

    // fork: MLP GEMM chain on s2 (independent of CSR build; no dinv needed)
    cudaEventRecord(e0, 0);
    cudaStreamWaitEvent(s2, e0, 0);
    k_gemm< 64, true><<<dim3(1, NROWB), 256, 0, s2>>>(h32b, wb2, h64b,  N, 32,  64,  b2, 1, 0);
    k_gemm<128, true><<<dim3(1, NROWB), 256, 0, s2>>>(h64b, wb3, h128b, N, 64,  128, b3, 1, 0);
    cudaEventRecord(e1, s2);

    // CSR chain on main stream
    k_scan1<<<NBLK, 256>>>();                      // also computes dinv
    k_scan23<<<NBLK, 256>>>();
    k_bucket<<<(NEDGES + 255) / 256, 256>>>(eidx);

    // join
    cudaStreamWaitEvent(0, e1, 0);

    // GCN 1: aggregate inputs (scaling sources by dinv), then GEMM bias+relu+dinv
    k_agg128<<<(N + 15) / 16, 256>>>(h128b, u128);
    k_gemm<128, true><<<dim3(2, NROWB), 256>>>(u128, wg1, a256, N, 128, 256, g1b, 1, 1);

    // GCN 2
    k_agg256<<<NAGGB, 256>>>(a256, u256);
    k_gemm<128, true><<<dim3(4, NROWB), 256>>>(u256, wg2, a512, N, 256, 512, g2b, 1, 1);

    // GCN 3: GEMM first (narrow output), aggregate after + softmax
    k_gemm<64, false><<<dim3(1, NROWB), 256>>>(a512, wg3, t50, N, 512, 64, nullptr, 0, 0);
    k_agg_softmax<<<NAGGB, 256>>>(t50, out, g3b);
}

// round 15
// speedup vs baseline: 1.0261x; 1.0157x over previous
#include <cuda_runtime.h>
#include <cuda_bf16.h>
#include <mma.h>
#include <math.h>

using namespace nvcuda;
typedef __nv_bfloat16 bf16;

// ---------------- problem constants ----------------
#define NNODES 50000
#define NEDGES 800000
#define NBLK   ((NNODES + 255) / 256)   // 196

// ---------------- device scratch ----------------
__device__ unsigned g_any;
__device__ int   g_cnt[NNODES];
__device__ int   g_rowptr[NNODES + 1];
__device__ int   g_ctr[NNODES];
__device__ int   g_csr[NEDGES];
__device__ float g_dinv[NNODES];
__device__ int   g_bsum[NBLK];

__device__ bf16  g_h32b [NNODES * 32];
__device__ bf16  g_h64b [NNODES * 64];
__device__ bf16  g_h128b[NNODES * 128];   // relu(mlp3)  (NO dinv — applied in agg)
__device__ bf16  g_u128 [NNODES * 128];   // aggregated
__device__ bf16  g_a256 [NNODES * 256];   // relu(gcn1) * dinv
__device__ bf16  g_u256 [NNODES * 256];
__device__ bf16  g_a512 [NNODES * 512];   // relu(gcn2) * dinv
__device__ float g_t50  [NNODES * 64];    // padded, pre-agg logits

__device__ bf16  g_wb2[32 * 64];
__device__ bf16  g_wb3[64 * 128];
__device__ bf16  g_wg1[128 * 256];
__device__ bf16  g_wg2[256 * 512];
__device__ bf16  g_wg3[512 * 64];         // zero-padded 50 -> 64

// ---------------- edge-index dtype handling ----------------
__device__ __forceinline__ int load_idx(const void* p, long long e) {
    if (g_any == 0u) return (int)((const long long*)p)[e];   // int64 data
    return ((const int*)p)[e];
}

#define FTHREADS (NBLK * 256)   // 50176

// ---------------- detect + zero counters (must precede k_front's atomics) ----------------
__global__ void k_detect(const unsigned* __restrict__ e32) {
    int gid = blockIdx.x * 256 + threadIdx.x;
    if (gid < NNODES) g_cnt[gid] = 0;
    unsigned local = (gid < 16384) ? e32[2 * gid + 1] : 0u;
    #pragma unroll
    for (int off = 16; off > 0; off >>= 1) local |= __shfl_xor_sync(0xffffffffu, local, off);
    if ((threadIdx.x & 31) == 0 && local) atomicOr(&g_any, local);
}

// ---------------- merged front: degree + weight cvt + MLP1 ----------------
#define WN2 (32*64)
#define WN3 (64*128)
#define WG1 (128*256)
#define WG2 (256*512)
#define WG3P (512*64)
#define WTOT (WN2 + WN3 + WG1 + WG2 + WG3P)

__global__ __launch_bounds__(256) void k_front(
    const void* __restrict__ eidx,
    const float* __restrict__ x,  const float* __restrict__ w1, const float* __restrict__ b1,
    const float* __restrict__ w2, const float* __restrict__ w3,
    const float* __restrict__ g1w, const float* __restrict__ g2w, const float* __restrict__ g3w,
    bf16* __restrict__ h32out)
{
    __shared__ float sw[96];
    __shared__ float sb[32];
    int t   = threadIdx.x;
    int gid = blockIdx.x * 256 + t;
    if (t < 96) sw[t] = w1[t];
    if (t < 32) sb[t] = b1[t];

    // degree count
    for (long long e = gid; e < NEDGES; e += FTHREADS) {
        int d = load_idx(eidx, (long long)NEDGES + e);
        atomicAdd(&g_cnt[d], 1);
    }

    // weight conversion
    for (int j = gid; j < WTOT; j += FTHREADS) {
        int i = j;
        if (i < WN2) { g_wb2[i] = __float2bfloat16(w2[i]); continue; }
        i -= WN2;
        if (i < WN3) { g_wb3[i] = __float2bfloat16(w3[i]); continue; }
        i -= WN3;
        if (i < WG1) { g_wg1[i] = __float2bfloat16(g1w[i]); continue; }
        i -= WG1;
        if (i < WG2) { g_wg2[i] = __float2bfloat16(g2w[i]); continue; }
        i -= WG2;
        int r = i >> 6, c = i & 63;
        g_wg3[i] = __float2bfloat16((c < 50) ? g3w[r * 50 + c] : 0.f);
    }

    // MLP layer 1 (3 -> 32)
    __syncthreads();
    if (gid < NNODES) {
        float x0 = x[gid * 3 + 0], x1 = x[gid * 3 + 1], x2 = x[gid * 3 + 2];
        unsigned pk[16];
        #pragma unroll
        for (int j2 = 0; j2 < 16; j2++) {
            float v0 = fmaxf(fmaf(x0, sw[2*j2],   fmaf(x1, sw[32 + 2*j2],   fmaf(x2, sw[64 + 2*j2],   sb[2*j2]))),   0.f);
            float v1 = fmaxf(fmaf(x0, sw[2*j2+1], fmaf(x1, sw[32 + 2*j2+1], fmaf(x2, sw[64 + 2*j2+1], sb[2*j2+1]))), 0.f);
            __nv_bfloat162 p = __float22bfloat162_rn(make_float2(v0, v1));
            pk[j2] = *(unsigned*)&p;
        }
        uint4* o = (uint4*)(h32out + (long long)gid * 32);
        #pragma unroll
        for (int q = 0; q < 4; q++)
            o[q] = make_uint4(pk[4*q], pk[4*q+1], pk[4*q+2], pk[4*q+3]);
    }
}

// ---------------- scans ----------------
__device__ __forceinline__ int warp_iscan(int v, int lane) {
    #pragma unroll
    for (int off = 1; off < 32; off <<= 1) {
        int u = __shfl_up_sync(0xffffffffu, v, off);
        if (lane >= off) v += u;
    }
    return v;
}

__global__ void k_scan1() {
    __shared__ int wsum[8];
    int t = threadIdx.x, lane = t & 31, w = t >> 5;
    int i = blockIdx.x * 256 + t;
    int v = (i < NNODES) ? g_cnt[i] : 0;
    if (i < NNODES) g_dinv[i] = rsqrtf((float)(v + 1));
    int incl = warp_iscan(v, lane);
    if (lane == 31) wsum[w] = incl;
    __syncthreads();
    if (w == 0) {
        int s = (lane < 8) ? wsum[lane] : 0;
        s = warp_iscan(s, lane);
        if (lane < 8) wsum[lane] = s;
    }
    __syncthreads();
    int woff = (w > 0) ? wsum[w - 1] : 0;
    if (i < NNODES) g_rowptr[i] = woff + incl - v;
    if (t == 255) g_bsum[blockIdx.x] = woff + incl;
}

// merged scan2+scan3: each block redundantly reduces bsum[0..b-1] (L2-hot)
__global__ void k_scan23() {
    __shared__ int red[256];
    int b = blockIdx.x, t = threadIdx.x;
    int partial = 0;
    for (int j = t; j < b; j += 256) partial += g_bsum[j];
    red[t] = partial;
    __syncthreads();
    #pragma unroll
    for (int off = 128; off > 0; off >>= 1) {
        if (t < off) red[t] += red[t + off];
        __syncthreads();
    }
    int s_off = red[0];
    int i = b * 256 + t;
    if (i < NNODES) {
        int rp = g_rowptr[i] + s_off;
        g_rowptr[i] = rp;
        g_ctr[i]    = rp;
    }
    if (b == NBLK - 1 && t == 0) g_rowptr[NNODES] = s_off + g_bsum[b];
}

__global__ void k_bucket(const void* __restrict__ eidx) {
    int e = blockIdx.x * blockDim.x + threadIdx.x;
    if (e >= NEDGES) return;
    int s = load_idx(eidx, e);
    int d = load_idx(eidx, (long long)NEDGES + e);
    int pos = atomicAdd(&g_ctr[d], 1);
    g_csr[pos] = s;
}

// ---------------- cp.async helpers ----------------
__device__ __forceinline__ void cp16(void* dst, const void* src, bool pred) {
    unsigned s = (unsigned)__cvta_generic_to_shared(dst);
    int bytes = pred ? 16 : 0;
    asm volatile("cp.async.cg.shared.global [%0], [%1], 16, %2;\n" :: "r"(s), "l"(src), "r"(bytes));
}
__device__ __forceinline__ void cp_commit() { asm volatile("cp.async.commit_group;\n"); }
template <int N>
__device__ __forceinline__ void cp_wait() { asm volatile("cp.async.wait_group %0;\n" :: "n"(N)); }

// ---------------- bf16 WMMA GEMM: BM=64, 8 warps (2x4), 3 CTAs/SM target ----------------
#define GBM 64
#define ASTR 40

template <int BNT, bool OUTBF>
__global__ __launch_bounds__(256, 3) void k_gemm(
    const bf16* __restrict__ A, const bf16* __restrict__ B, void* __restrict__ Cv,
    int N, int K, int M,
    const float* __restrict__ bias, int do_relu, int dinv_after)
{
    constexpr int BSTR  = BNT + 8;
    constexpr int ABYTES = GBM * ASTR * 2;            // 5120
    constexpr int STAGE  = ABYTES + 32 * BSTR * 2;
    constexpr int CSTR   = BNT + 4;
    constexpr int FW     = BNT / 4;                   // warp col width: 32 or 16
    constexpr int FN     = FW / 16;                   // frags along N: 2 or 1
    constexpr int SMEMB  = (2 * STAGE > GBM * CSTR * 4) ? 2 * STAGE : GBM * CSTR * 4;

    __shared__ __align__(16) char smem_raw[SMEMB];

    int tid  = threadIdx.x;
    int warp = tid >> 5;
    int wr = warp >> 2, wc = warp & 3;                // 2 x 4 warp grid
    int row0 = blockIdx.y * GBM;
    int col0 = blockIdx.x * BNT;

    wmma::fragment<wmma::accumulator, 16, 16, 16, float> acc[2][FN];
    #pragma unroll
    for (int i = 0; i < 2; i++)
        #pragma unroll
        for (int j = 0; j < FN; j++) wmma::fill_fragment(acc[i][j], 0.f);

    // A tile: 64 x 32 bf16 = 256 16B chunks -> 1 per thread.
    // B tile: 32 x BNT -> 4*BNT chunks -> 2/thread @128, 1/thread @64.
    auto loadStage = [&](int k0, int st) {
        bf16* As = (bf16*)(smem_raw + st * STAGE);
        bf16* Bs = (bf16*)(smem_raw + st * STAGE + ABYTES);
        {
            int r = tid >> 2, c = tid & 3;            // r in [0,64), c in [0,4)
            int gr = row0 + r;
            bool ok = gr < N;
            const bf16* src = A + (size_t)(ok ? gr : N - 1) * K + k0 + c * 8;
            cp16(As + r * ASTR + c * 8, src, ok);
        }
        constexpr int CPB = BNT / 8;
        #pragma unroll
        for (int i = 0; i < (4 * BNT) / 256; i++) {
            int id = tid + i * 256;
            int r = id / CPB, c = id % CPB;
            cp16(Bs + r * BSTR + c * 8, B + (size_t)(k0 + r) * M + col0 + c * 8, true);
        }
        cp_commit();
    };

    int nk = K >> 5;
    loadStage(0, 0);

    for (int kt = 0; kt < nk; kt++) {
        if (kt + 1 < nk) { loadStage((kt + 1) << 5, (kt + 1) & 1); cp_wait<1>(); }
        else             { cp_wait<0>(); }
        __syncthreads();

        bf16* As = (bf16*)(smem_raw + (kt & 1) * STAGE);
        bf16* Bs = (bf16*)(smem_raw + (kt & 1) * STAGE + ABYTES);
        #pragma unroll
        for (int kk = 0; kk < 32; kk += 16) {
            wmma::fragment<wmma::matrix_a, 16, 16, 16, bf16, wmma::row_major> af[2];
            wmma::fragment<wmma::matrix_b, 16, 16, 16, bf16, wmma::row_major> bfr[FN];
            #pragma unroll
            for (int i = 0; i < 2; i++)
                wmma::load_matrix_sync(af[i], As + (wr * 32 + i * 16) * ASTR + kk, ASTR);
            #pragma unroll
            for (int j = 0; j < FN; j++)
                wmma::load_matrix_sync(bfr[j], Bs + kk * BSTR + wc * FW + j * 16, BSTR);
            #pragma unroll
            for (int i = 0; i < 2; i++)
                #pragma unroll
                for (int j = 0; j < FN; j++)
                    wmma::mma_sync(acc[i][j], af[i], bfr[j], acc[i][j]);
        }
        __syncthreads();
    }

    // single-phase epilogue: 64 rows staged at once
    float* Cs = (float*)smem_raw;
    #pragma unroll
    for (int i = 0; i < 2; i++)
        #pragma unroll
        for (int j = 0; j < FN; j++)
            wmma::store_matrix_sync(Cs + (size_t)(wr * 32 + i * 16) * CSTR + wc * FW + j * 16,
                                    acc[i][j], CSTR, wmma::mem_row_major);
    __syncthreads();

    constexpr int G = BNT / 4;                    // float4 groups per row
    #pragma unroll
    for (int i = 0; i < (GBM * G) / 256; i++) {
        int id = tid + i * 256;
        int r = id / G, c4 = id % G;
        int gr = row0 + r;
        if (gr < N) {
            float* s = Cs + (size_t)r * CSTR + c4 * 4;
            float4 v = make_float4(s[0], s[1], s[2], s[3]);
            if (bias) {
                const float* bb = bias + col0 + c4 * 4;
                v.x += bb[0]; v.y += bb[1]; v.z += bb[2]; v.w += bb[3];
            }
            if (do_relu) {
                v.x = fmaxf(v.x, 0.f); v.y = fmaxf(v.y, 0.f);
                v.z = fmaxf(v.z, 0.f); v.w = fmaxf(v.w, 0.f);
            }
            if (dinv_after) {
                float d = g_dinv[gr];
                v.x *= d; v.y *= d; v.z *= d; v.w *= d;
            }
            if (OUTBF) {
                __nv_bfloat162 p0 = __float22bfloat162_rn(make_float2(v.x, v.y));
                __nv_bfloat162 p1 = __float22bfloat162_rn(make_float2(v.z, v.w));
                uint2 pk = make_uint2(*(unsigned*)&p0, *(unsigned*)&p1);
                *(uint2*)((bf16*)Cv + (size_t)gr * M + col0 + c4 * 4) = pk;
            } else {
                *(float4*)((float*)Cv + (size_t)gr * M + col0 + c4 * 4) = v;
            }
        }
    }
}

// ---------------- F=128 aggregation: half-warp (16 lanes x 16B) per node, source dinv ----------------
__global__ __launch_bounds__(256) void k_agg128(
    const bf16* __restrict__ ts, bf16* __restrict__ out)
{
    int lane16 = threadIdx.x & 15;
    int node = blockIdx.x * 16 + (threadIdx.x >> 4);
    if (node >= NNODES) return;

    float di = g_dinv[node];
    float acc[8];
    {
        uint4 v = *(const uint4*)(ts + (size_t)node * 128 + lane16 * 8);
        float2 f0 = __bfloat1622float2(*(__nv_bfloat162*)&v.x);
        float2 f1 = __bfloat1622float2(*(__nv_bfloat162*)&v.y);
        float2 f2 = __bfloat1622float2(*(__nv_bfloat162*)&v.z);
        float2 f3 = __bfloat1622float2(*(__nv_bfloat162*)&v.w);
        acc[0] = f0.x * di; acc[1] = f0.y * di; acc[2] = f1.x * di; acc[3] = f1.y * di;
        acc[4] = f2.x * di; acc[5] = f2.y * di; acc[6] = f3.x * di; acc[7] = f3.y * di;
    }

    auto addRow = [&](int s) {
        float ds = g_dinv[s];
        uint4 v = *(const uint4*)(ts + (size_t)s * 128 + lane16 * 8);
        float2 f0 = __bfloat1622float2(*(__nv_bfloat162*)&v.x);
        float2 f1 = __bfloat1622float2(*(__nv_bfloat162*)&v.y);
        float2 f2 = __bfloat1622float2(*(__nv_bfloat162*)&v.z);
        float2 f3 = __bfloat1622float2(*(__nv_bfloat162*)&v.w);
        acc[0] = fmaf(f0.x, ds, acc[0]); acc[1] = fmaf(f0.y, ds, acc[1]);
        acc[2] = fmaf(f1.x, ds, acc[2]); acc[3] = fmaf(f1.y, ds, acc[3]);
        acc[4] = fmaf(f2.x, ds, acc[4]); acc[5] = fmaf(f2.y, ds, acc[5]);
        acc[6] = fmaf(f3.x, ds, acc[6]); acc[7] = fmaf(f3.y, ds, acc[7]);
    };

    int e = g_rowptr[node], end = g_rowptr[node + 1];
    for (; e + 8 <= end; e += 8) {
        int s[8];
        #pragma unroll
        for (int j = 0; j < 8; j++) s[j] = g_csr[e + j];
        #pragma unroll
        for (int j = 0; j < 8; j++) addRow(s[j]);
    }
    for (; e < end; e++) addRow(g_csr[e]);

    bf16* o = out + (size_t)node * 128 + lane16 * 8;
    #pragma unroll
    for (int p = 0; p < 4; p++) {
        __nv_bfloat162 pk = __float22bfloat162_rn(make_float2(acc[2*p] * di, acc[2*p+1] * di));
        *(__nv_bfloat162*)(o + 2 * p) = pk;
    }
}

// ---------------- F=256 aggregation: warp per node (pre-scaled input) ----------------
__global__ __launch_bounds__(256) void k_agg256(
    const bf16* __restrict__ ts, bf16* __restrict__ out)
{
    int lane = threadIdx.x & 31;
    int node = blockIdx.x * 8 + (threadIdx.x >> 5);
    if (node >= NNODES) return;

    float acc[8];
    {
        uint4 v = *(const uint4*)(ts + (size_t)node * 256 + lane * 8);
        float2 f0 = __bfloat1622float2(*(__nv_bfloat162*)&v.x);
        float2 f1 = __bfloat1622float2(*(__nv_bfloat162*)&v.y);
        float2 f2 = __bfloat1622float2(*(__nv_bfloat162*)&v.z);
        float2 f3 = __bfloat1622float2(*(__nv_bfloat162*)&v.w);
        acc[0] = f0.x; acc[1] = f0.y; acc[2] = f1.x; acc[3] = f1.y;
        acc[4] = f2.x; acc[5] = f2.y; acc[6] = f3.x; acc[7] = f3.y;
    }

    auto addRow = [&](int s) {
        uint4 v = *(const uint4*)(ts + (size_t)s * 256 + lane * 8);
        float2 f0 = __bfloat1622float2(*(__nv_bfloat162*)&v.x);
        float2 f1 = __bfloat1622float2(*(__nv_bfloat162*)&v.y);
        float2 f2 = __bfloat1622float2(*(__nv_bfloat162*)&v.z);
        float2 f3 = __bfloat1622float2(*(__nv_bfloat162*)&v.w);
        acc[0] += f0.x; acc[1] += f0.y; acc[2] += f1.x; acc[3] += f1.y;
        acc[4] += f2.x; acc[5] += f2.y; acc[6] += f3.x; acc[7] += f3.y;
    };

    int e = g_rowptr[node], end = g_rowptr[node + 1];
    for (; e + 8 <= end; e += 8) {
        int s[8];
        #pragma unroll
        for (int j = 0; j < 8; j++) s[j] = g_csr[e + j];
        #pragma unroll
        for (int j = 0; j < 8; j++) addRow(s[j]);
    }
    for (; e + 4 <= end; e += 4) {
        int s[4];
        #pragma unroll
        for (int j = 0; j < 4; j++) s[j] = g_csr[e + j];
        #pragma unroll
        for (int j = 0; j < 4; j++) addRow(s[j]);
    }
    for (; e < end; e++) addRow(g_csr[e]);

    float di = g_dinv[node];
    bf16* o = out + (size_t)node * 256 + lane * 8;
    #pragma unroll
    for (int p = 0; p < 4; p++) {
        __nv_bfloat162 pk = __float22bfloat162_rn(make_float2(acc[2*p] * di, acc[2*p+1] * di));
        *(__nv_bfloat162*)(o + 2 * p) = pk;
    }
}

// ---------------- final aggregation + softmax: warp per node ----------------
__global__ __launch_bounds__(256) void k_agg_softmax(
    const float* __restrict__ ts, float* __restrict__ out, const float* __restrict__ bias)
{
    int lane = threadIdx.x & 31;
    int node = blockIdx.x * 8 + (threadIdx.x >> 5);
    if (node >= NNODES) return;

    const float2* tsv = (const float2*)ts;          // 32 float2 per row
    float2 acc = tsv[(size_t)node * 32 + lane];     // self
    int e = g_rowptr[node], end = g_rowptr[node + 1];
    for (; e + 8 <= end; e += 8) {
        int s[8];
        #pragma unroll
        for (int j = 0; j < 8; j++) s[j] = g_csr[e + j];
        #pragma unroll
        for (int j = 0; j < 8; j++) {
            float2 v = tsv[(size_t)s[j] * 32 + lane];
            acc.x += v.x; acc.y += v.y;
        }
    }
    for (; e < end; e++) {
        float2 v = tsv[(size_t)g_csr[e] * 32 + lane];
        acc.x += v.x; acc.y += v.y;
    }

    float di = g_dinv[node];
    float vx = -INFINITY, vy = -INFINITY;
    if (lane < 25) {
        const float2 bb = *(const float2*)(bias + 2 * lane);
        vx = fmaf(di, acc.x, bb.x);
        vy = fmaf(di, acc.y, bb.y);
    }
    float m = fmaxf(vx, vy);
    #pragma unroll
    for (int off = 16; off > 0; off >>= 1) m = fmaxf(m, __shfl_xor_sync(0xffffffffu, m, off));
    float ex = (lane < 25) ? expf(vx - m) : 0.f;
    float ey = (lane < 25) ? expf(vy - m) : 0.f;
    float ssum = ex + ey;
    #pragma unroll
    for (int off = 16; off > 0; off >>= 1) ssum += __shfl_xor_sync(0xffffffffu, ssum, off);
    if (lane < 25) {
        float inv = 1.f / ssum;
        *(float2*)(out + (size_t)node * 50 + 2 * lane) = make_float2(ex * inv, ey * inv);
    }
}

// ---------------- launch ----------------
extern "C" void kernel_launch(void* const* d_in, const int* in_sizes, int n_in,
                              void* d_out, int out_size)
{
    const float* x    = (const float*)d_in[0];
    const void*  eidx = d_in[1];
    const float* w1 = (const float*)d_in[2],  *b1 = (const float*)d_in[3];
    const float* w2 = (const float*)d_in[4];
    const float* b2 = (const float*)d_in[5];
    const float* w3 = (const float*)d_in[6],  *b3 = (const float*)d_in[7];
    const float* g1w = (const float*)d_in[8],  *g1b = (const float*)d_in[9];
    const float* g2w = (const float*)d_in[10], *g2b = (const float*)d_in[11];
    const float* g3w = (const float*)d_in[12], *g3b = (const float*)d_in[13];
    float* out = (float*)d_out;

    bf16 *h32b, *h64b, *h128b, *u128, *a256, *u256, *a512;
    bf16 *wb2, *wb3, *wg1, *wg2, *wg3;
    float *t50;
    cudaGetSymbolAddress((void**)&h32b,  g_h32b);
    cudaGetSymbolAddress((void**)&h64b,  g_h64b);
    cudaGetSymbolAddress((void**)&h128b, g_h128b);
    cudaGetSymbolAddress((void**)&u128,  g_u128);
    cudaGetSymbolAddress((void**)&a256,  g_a256);
    cudaGetSymbolAddress((void**)&u256,  g_u256);
    cudaGetSymbolAddress((void**)&a512,  g_a512);
    cudaGetSymbolAddress((void**)&t50,   g_t50);
    cudaGetSymbolAddress((void**)&wb2,   g_wb2);
    cudaGetSymbolAddress((void**)&wb3,   g_wb3);
    cudaGetSymbolAddress((void**)&wg1,   g_wg1);
    cudaGetSymbolAddress((void**)&wg2,   g_wg2);
    cudaGetSymbolAddress((void**)&wg3,   g_wg3);

    const int N = NNODES;
    const int NROWB = (N + GBM - 1) / GBM;   // 782
    const int NAGGB = (N + 7) / 8;           // 6250

    // one-time setup (first call = correctness run, outside capture)
    static cudaStream_t s2 = nullptr;
    static cudaEvent_t  e0 = nullptr, e1 = nullptr;
    if (!s2) {
        cudaStreamCreateWithFlags(&s2, cudaStreamNonBlocking);
        cudaEventCreateWithFlags(&e0, cudaEventDisableTiming);
        cudaEventCreateWithFlags(&e1, cudaEventDisableTiming);
    }

    // detect dtype + zero counters (must precede front's degree atomics)
    k_detect<<<NBLK, 256>>>((const unsigned*)eidx);

    // front: degree + weight cvt + MLP1
    k_front<<<NBLK, 256>>>(eidx, x, w1, b1, w2, w3, g1w, g2w, g3w, h32b);

    // fork: MLP GEMM chain on s2 (independent of CSR build; no dinv needed)
    cudaEventRecord(e0, 0);
    cudaStreamWaitEvent(s2, e0, 0);
    k_gemm< 64, true><<<dim3(1, NROWB), 256, 0, s2>>>(h32b, wb2, h64b,  N, 32,  64,  b2, 1, 0);
    k_gemm<128, true><<<dim3(1, NROWB), 256, 0, s2>>>(h64b, wb3, h128b, N, 64,  128, b3, 1, 0);
    cudaEventRecord(e1, s2);

    // CSR chain on main stream
    k_scan1<<<NBLK, 256>>>();                      // also computes dinv
    k_scan23<<<NBLK, 256>>>();
    k_bucket<<<(NEDGES + 255) / 256, 256>>>(eidx);

    // join
    cudaStreamWaitEvent(0, e1, 0);

    // GCN 1: aggregate inputs (scaling sources by dinv), then GEMM bias+relu+dinv
    k_agg128<<<(N + 15) / 16, 256>>>(h128b, u128);
    k_gemm<128, true><<<dim3(2, NROWB), 256>>>(u128, wg1, a256, N, 128, 256, g1b, 1, 1);

    // GCN 2
    k_agg256<<<NAGGB, 256>>>(a256, u256);
    k_gemm<128, true><<<dim3(4, NROWB), 256>>>(u256, wg2, a512, N, 256, 512, g2b, 1, 1);

    // GCN 3: GEMM first (narrow output), aggregate after + softmax
    k_gemm<64, false><<<dim3(1, NROWB), 256>>>(a512, wg3, t50, N, 512, 64, nullptr, 0, 0);
    k_agg_softmax<<<NAGGB, 256>>>(t50, out, g3b);
}